// round 6
// baseline (speedup 1.0000x reference)
#include <cuda_runtime.h>
#include <cstdint>

#define SEQ    128
#define BATCH  64
#define HID    1024
#define VOCABN 5000

// -------- scratch (device globals: allocation-free) --------
__device__ float g_y1 [SEQ * BATCH * HID];
__device__ float g_y2 [SEQ * BATCH * HID];
__device__ float g_xp2[SEQ * BATCH * HID];

// -------- f32x2 helpers (full-rate packed FMA on sm_103a) --------
static __device__ __forceinline__ unsigned long long pack2(float lo, float hi) {
    unsigned long long r; asm("mov.b64 %0,{%1,%2};" : "=l"(r) : "f"(lo), "f"(hi)); return r;
}
static __device__ __forceinline__ unsigned long long dup2(float v) {
    unsigned long long r; asm("mov.b64 %0,{%1,%1};" : "=l"(r) : "f"(v)); return r;
}
static __device__ __forceinline__ void unpack2(unsigned long long v, float& lo, float& hi) {
    asm("mov.b64 {%0,%1},%2;" : "=f"(lo), "=f"(hi) : "l"(v));
}
static __device__ __forceinline__ void ffma2(unsigned long long& c,
                                             unsigned long long a, unsigned long long b) {
    asm("fma.rn.f32x2 %0,%1,%2,%0;" : "+l"(c) : "l"(a), "l"(b));
}

// ============================================================================
// One recurrence step: h_new[b,g] = tanh(add[b,g] + h_prev[b,:]·W_hh[g,:] + b_hh[g])
// LAYER==1: add = W_ih1[g, x[t,b]] + b_ih1[g]     LAYER==2: add = g_xp2[t,b,g]
// grid=128 CTAs (8 g each), block=256 (warp w -> batches 8w..8w+7, lanes split K)
// ============================================================================
template <int LAYER>
__global__ void __launch_bounds__(256, 1)
rnn_step(int t, const int* __restrict__ x,
         const float* __restrict__ W_hh, const float* __restrict__ b_hh,
         const float* __restrict__ W_ih1, const float* __restrict__ b_ih1)
{
    __shared__ __align__(16) float sbuf[8448];   // W slice (8192) then reduction (8448)
    float* ybuf = (LAYER == 1) ? g_y1 : g_y2;

    const int tid  = threadIdx.x;
    const int lane = tid & 31;
    const int w    = tid >> 5;
    const int g0   = blockIdx.x * 8;

    {   // stage W_hh rows [g0, g0+8) -> smem (32 KB), coalesced
        const float4* Wg  = (const float4*)(W_hh + (size_t)g0 * HID);
        float4*       ws4 = (float4*)sbuf;
#pragma unroll
        for (int it = 0; it < 8; it++) ws4[tid + 256 * it] = Wg[tid + 256 * it];
    }
    __syncthreads();

    unsigned long long acc[8][4];
#pragma unroll
    for (int i = 0; i < 8; i++)
#pragma unroll
        for (int q = 0; q < 4; q++) acc[i][q] = 0ull;

    if (t > 0) {
        const float* hprev  = ybuf + (size_t)(t - 1) * (BATCH * HID);
        const int    b_base = w * 8;
#pragma unroll
        for (int j = 0; j < 8; j++) {
            const int k0 = 4 * lane + 128 * j;
            float4 hv[8], wv[8];
#pragma unroll
            for (int i = 0; i < 8; i++)
                hv[i] = *(const float4*)(hprev + (size_t)(b_base + i) * HID + k0);
#pragma unroll
            for (int g = 0; g < 8; g++)
                wv[g] = *(const float4*)(sbuf + g * HID + k0);
#pragma unroll
            for (int kk = 0; kk < 4; kk++) {
                unsigned long long bd[4];
#pragma unroll
                for (int q = 0; q < 4; q++)
                    bd[q] = pack2(((const float*)&wv[2 * q])[kk],
                                  ((const float*)&wv[2 * q + 1])[kk]);
#pragma unroll
                for (int i = 0; i < 8; i++) {
                    const unsigned long long ad = dup2(((const float*)&hv[i])[kk]);
#pragma unroll
                    for (int q = 0; q < 4; q++) ffma2(acc[i][q], ad, bd[q]);
                }
            }
        }
    }
    __syncthreads();                             // sbuf -> reduction space

    float* red = sbuf;
#pragma unroll
    for (int i = 0; i < 8; i++)
#pragma unroll
        for (int q = 0; q < 4; q++) {
            float lo, hi; unpack2(acc[i][q], lo, hi);
            lo += __shfl_xor_sync(0xffffffffu, lo, 16);
            hi += __shfl_xor_sync(0xffffffffu, hi, 16);
            if (lane < 16) {
                const int row = (w * 16 + lane) * 66;
                red[row + i * 8 + q * 2]     = lo;
                red[row + i * 8 + q * 2 + 1] = hi;
            }
        }
    __syncwarp();

#pragma unroll
    for (int rep = 0; rep < 2; rep++) {
        const int o = lane + 32 * rep;           // o = i*8 + g_local
        float s = 0.f;
#pragma unroll
        for (int m = 0; m < 16; m++) s += red[(w * 16 + m) * 66 + o];
        const int b = w * 8 + (o >> 3);
        const int g = g0 + (o & 7);
        float add;
        if (LAYER == 1) add = W_ih1[(size_t)g * VOCABN + x[t * BATCH + b]] + b_ih1[g] + b_hh[g];
        else            add = g_xp2[(size_t)(t * BATCH + b) * HID + g] + b_hh[g];
        ybuf[(size_t)(t * BATCH + b) * HID + g] = tanhf(s + add);
    }
}

// ============================================================================
// C[M,N] = A[M,K]·B[N,K]^T + bias[N]   (K=1024, M=8192, N runtime)
// CTA 128x128, 256 thr, thread tile 8m x 8n (4 f32x2 pairs), K-chunk 32
// ============================================================================
__global__ void __launch_bounds__(256, 1)
gemm_nt_bias(const float* __restrict__ A, const float* __restrict__ B,
             const float* __restrict__ bias, float* __restrict__ C, int N)
{
    __shared__ __align__(16) float As[32][132];
    __shared__ __align__(16) float Bs[32][132];

    const int tid   = threadIdx.x;
    const int tx    = tid & 15;
    const int ty    = tid >> 4;
    const int m0    = ty * 8;
    const int mtile = blockIdx.y * 128;
    const int ntile = blockIdx.x * 128;
    const int kq    = tid & 7;
    const int mrow  = tid >> 3;

    float4 ar[4], br[4];
#pragma unroll
    for (int it = 0; it < 4; it++) {
        const int m = mrow + 32 * it;
        ar[it] = *(const float4*)(A + (size_t)(mtile + m) * 1024 + 4 * kq);
        const int n = ntile + m;
        br[it] = (n < N) ? *(const float4*)(B + (size_t)n * 1024 + 4 * kq)
                         : make_float4(0.f, 0.f, 0.f, 0.f);
    }
#pragma unroll
    for (int it = 0; it < 4; it++) {
        const int m = mrow + 32 * it;
#pragma unroll
        for (int jj = 0; jj < 4; jj++) {
            As[4 * kq + jj][m] = ((const float*)&ar[it])[jj];
            Bs[4 * kq + jj][m] = ((const float*)&br[it])[jj];
        }
    }
    __syncthreads();

    unsigned long long acc[8][4];
#pragma unroll
    for (int i = 0; i < 8; i++)
#pragma unroll
        for (int q = 0; q < 4; q++) acc[i][q] = 0ull;

    for (int kc = 0; kc < 1024; kc += 32) {
        const bool last = (kc + 32 >= 1024);
        if (!last) {
#pragma unroll
            for (int it = 0; it < 4; it++) {
                const int m = mrow + 32 * it;
                ar[it] = *(const float4*)(A + (size_t)(mtile + m) * 1024 + kc + 32 + 4 * kq);
                const int n = ntile + m;
                br[it] = (n < N) ? *(const float4*)(B + (size_t)n * 1024 + kc + 32 + 4 * kq)
                                 : make_float4(0.f, 0.f, 0.f, 0.f);
            }
        }
#pragma unroll
        for (int k = 0; k < 32; k++) {
            float a[8];
            *(float4*)(a)     = *(const float4*)&As[k][m0];
            *(float4*)(a + 4) = *(const float4*)&As[k][m0 + 4];
            unsigned long long bd[4];
#pragma unroll
            for (int q = 0; q < 4; q++)
                bd[q] = *(const unsigned long long*)&Bs[k][2 * tx + 32 * q];
#pragma unroll
            for (int i = 0; i < 8; i++) {
                const unsigned long long ad = dup2(a[i]);
#pragma unroll
                for (int q = 0; q < 4; q++) ffma2(acc[i][q], ad, bd[q]);
            }
        }
        __syncthreads();
        if (!last) {
#pragma unroll
            for (int it = 0; it < 4; it++) {
                const int m = mrow + 32 * it;
#pragma unroll
                for (int jj = 0; jj < 4; jj++) {
                    As[4 * kq + jj][m] = ((const float*)&ar[it])[jj];
                    Bs[4 * kq + jj][m] = ((const float*)&br[it])[jj];
                }
            }
            __syncthreads();
        }
    }

#pragma unroll
    for (int i = 0; i < 8; i++) {
        float* cr = C + (size_t)(mtile + m0 + i) * N;
#pragma unroll
        for (int q = 0; q < 4; q++) {
            const int n = ntile + 2 * tx + 32 * q;
            float lo, hi; unpack2(acc[i][q], lo, hi);
            if (n < N)     cr[n]     = lo + bias[n];
            if (n + 1 < N) cr[n + 1] = hi + bias[n + 1];
        }
    }
}

// state = stack([h1_last, h2_last])  -> out tail, 2*B*H elements
__global__ void copy_state(float* __restrict__ out)
{
    const int i = blockIdx.x * 256 + threadIdx.x;            // 0..131071
    const int base = (SEQ - 1) * BATCH * HID;
    out[i] = (i < BATCH * HID) ? g_y1[base + i] : g_y2[base + i - BATCH * HID];
}

extern "C" void kernel_launch(void* const* d_in, const int* in_sizes, int n_in,
                              void* d_out, int out_size)
{
    const int*   x     = (const int*)  d_in[0];
    const float* W_ih1 = (const float*)d_in[1];
    const float* W_hh1 = (const float*)d_in[2];
    const float* b_ih1 = (const float*)d_in[3];
    const float* b_hh1 = (const float*)d_in[4];
    const float* W_ih2 = (const float*)d_in[5];
    const float* W_hh2 = (const float*)d_in[6];
    const float* b_ih2 = (const float*)d_in[7];
    const float* b_hh2 = (const float*)d_in[8];
    const float* W_fc  = (const float*)d_in[9];
    const float* b_fc  = (const float*)d_in[10];
    float*       out   = (float*)d_out;

    void *py1 = nullptr, *py2 = nullptr, *pxp2 = nullptr;
    cudaGetSymbolAddress(&py1,  g_y1);
    cudaGetSymbolAddress(&py2,  g_y2);
    cudaGetSymbolAddress(&pxp2, g_xp2);

    for (int t = 0; t < SEQ; t++)
        rnn_step<1><<<128, 256>>>(t, x, W_hh1, b_hh1, W_ih1, b_ih1);

    gemm_nt_bias<<<dim3(8, 64), 256>>>((const float*)py1, W_ih2, b_ih2, (float*)pxp2, HID);

    for (int t = 0; t < SEQ; t++)
        rnn_step<2><<<128, 256>>>(t, x, W_hh2, b_hh2, W_ih1, b_ih1);

    gemm_nt_bias<<<dim3(40, 64), 256>>>((const float*)py2, W_fc, b_fc, out, VOCABN);

    copy_state<<<512, 256>>>(out + (size_t)SEQ * BATCH * VOCABN);
}

// round 7
// speedup vs baseline: 1.0862x; 1.0862x over previous
#include <cuda_runtime.h>
#include <cstdint>

#define SEQ    128
#define BATCH  64
#define HID    1024
#define VOCABN 5000
#define NCTA   128

// -------- scratch (device globals: allocation-free) --------
__device__ float g_y1 [SEQ * BATCH * HID];
__device__ float g_y2 [SEQ * BATCH * HID];
__device__ float g_xp2[SEQ * BATCH * HID];
__device__ unsigned g_bar;   // monotone grid-barrier counter (zero-init)

// -------- f32x2 helpers (full-rate packed FMA on sm_103a) --------
static __device__ __forceinline__ unsigned long long pack2(float lo, float hi) {
    unsigned long long r; asm("mov.b64 %0,{%1,%2};" : "=l"(r) : "f"(lo), "f"(hi)); return r;
}
static __device__ __forceinline__ unsigned long long dup2(float v) {
    unsigned long long r; asm("mov.b64 %0,{%1,%1};" : "=l"(r) : "f"(v)); return r;
}
static __device__ __forceinline__ void unpack2(unsigned long long v, float& lo, float& hi) {
    asm("mov.b64 {%0,%1},%2;" : "=f"(lo), "=f"(hi) : "l"(v));
}
static __device__ __forceinline__ void ffma2(unsigned long long& c,
                                             unsigned long long a, unsigned long long b) {
    asm("fma.rn.f32x2 %0,%1,%2,%0;" : "+l"(c) : "l"(a), "l"(b));
}

// -------- software grid barrier (128 co-resident CTAs, monotone counter) ----
static __device__ __forceinline__ void grid_bar()
{
    __syncthreads();
    if (threadIdx.x == 0) {
        __threadfence();                                   // release my CTA's writes
        unsigned old = atomicAdd(&g_bar, 1u);              // arrive
        unsigned target = (old & ~(unsigned)(NCTA - 1)) + NCTA;
        unsigned v;
        do {
            asm volatile("ld.acquire.gpu.global.u32 %0,[%1];"
                         : "=r"(v) : "l"(&g_bar) : "memory");
        } while ((int)(v - target) < 0);                   // wrap-safe
    }
    __syncthreads();
}

// ============================================================================
// Persistent recurrence kernel: loops t=0..127 with grid barriers.
//   h[t][b,g] = tanh(add + h[t-1][b,:]·W_hh[g,:] + b_hh[g])
// LAYER==1: add = W_ih1[g, x[t,b]] + b_ih1[g]    LAYER==2: add = g_xp2[t,b,g]
// 128 CTAs (8 g each, W slice persistent in smem), 512 thr (16 warps).
// Warp w -> batches 4w..4w+3; lane covers k in {4*lane+128j}; tile 4b x 8g.
// ============================================================================
template <int LAYER>
__global__ void __launch_bounds__(512, 1)
rnn_persist(const int* __restrict__ x,
            const float* __restrict__ W_hh, const float* __restrict__ b_hh,
            const float* __restrict__ W_ih1, const float* __restrict__ b_ih1)
{
    extern __shared__ __align__(16) float sbuf[];   // [0,8192)=W  [8192,+8448)=red
    float* Wsh = sbuf;
    float* red = sbuf + 8192;

    float* ybuf = (LAYER == 1) ? g_y1 : g_y2;
    const int tid  = threadIdx.x;
    const int lane = tid & 31;
    const int w    = tid >> 5;
    const int g0   = blockIdx.x * 8;
    const int b_base = w * 4;

    {   // stage this CTA's 8 W_hh rows once (32 KB), coalesced
        const float4* Wg  = (const float4*)(W_hh + (size_t)g0 * HID);
        float4*       ws4 = (float4*)Wsh;
#pragma unroll
        for (int it = 0; it < 4; it++) ws4[tid + 512 * it] = Wg[tid + 512 * it];
    }
    __syncthreads();

    for (int t = 0; t < SEQ; t++) {
        if (t > 0) grid_bar();                      // y[t-1] is now globally visible

        unsigned long long acc[4][4];
#pragma unroll
        for (int i = 0; i < 4; i++)
#pragma unroll
            for (int q = 0; q < 4; q++) acc[i][q] = 0ull;

        if (t > 0) {
            const float* hprev = ybuf + (size_t)(t - 1) * (BATCH * HID);
#pragma unroll
            for (int j = 0; j < 8; j++) {
                const int k0 = 4 * lane + 128 * j;
                float4 hv[4], wv[8];
#pragma unroll
                for (int i = 0; i < 4; i++)
                    hv[i] = *(const float4*)(hprev + (size_t)(b_base + i) * HID + k0);
#pragma unroll
                for (int g = 0; g < 8; g++)
                    wv[g] = *(const float4*)(Wsh + g * HID + k0);
#pragma unroll
                for (int kk = 0; kk < 4; kk++) {
                    unsigned long long bd[4];
#pragma unroll
                    for (int q = 0; q < 4; q++)
                        bd[q] = pack2(((const float*)&wv[2 * q])[kk],
                                      ((const float*)&wv[2 * q + 1])[kk]);
#pragma unroll
                    for (int i = 0; i < 4; i++) {
                        const unsigned long long ad = dup2(((const float*)&hv[i])[kk]);
#pragma unroll
                        for (int q = 0; q < 4; q++) ffma2(acc[i][q], ad, bd[q]);
                    }
                }
            }
        }

        // ---- reduce 32 lane-partials: shfl_xor(16) then 16 smem rows (stride 33,
        // conflict-free), warp-local only ----
#pragma unroll
        for (int i = 0; i < 4; i++)
#pragma unroll
            for (int q = 0; q < 4; q++) {
                float lo, hi; unpack2(acc[i][q], lo, hi);
                lo += __shfl_xor_sync(0xffffffffu, lo, 16);
                hi += __shfl_xor_sync(0xffffffffu, hi, 16);
                if (lane < 16) {
                    float* row = red + (w * 16 + lane) * 33;
                    row[i * 8 + 2 * q]     = lo;
                    row[i * 8 + 2 * q + 1] = hi;
                }
            }
        __syncwarp();

        {   // one output per lane: o = lane -> (b, g)
            float s = 0.f;
#pragma unroll
            for (int m = 0; m < 16; m++) s += red[(w * 16 + m) * 33 + lane];
            const int b = b_base + (lane >> 3);
            const int g = g0 + (lane & 7);
            float add;
            if (LAYER == 1)
                add = W_ih1[(size_t)g * VOCABN + x[t * BATCH + b]] + b_ih1[g] + b_hh[g];
            else
                add = g_xp2[(size_t)(t * BATCH + b) * HID + g] + b_hh[g];
            ybuf[(size_t)(t * BATCH + b) * HID + g] = tanhf(s + add);
        }
        __syncwarp();   // reads of red done before next iteration rewrites it
    }
}

// ============================================================================
// C[M,N] = A[M,K]·B[N,K]^T + bias[N]   (K=1024, M=8192, N runtime)
// CTA 128x128, 256 thr, thread tile 8m x 8n (4 f32x2 pairs), K-chunk 32
// ============================================================================
__global__ void __launch_bounds__(256, 1)
gemm_nt_bias(const float* __restrict__ A, const float* __restrict__ B,
             const float* __restrict__ bias, float* __restrict__ C, int N)
{
    __shared__ __align__(16) float As[32][132];
    __shared__ __align__(16) float Bs[32][132];

    const int tid   = threadIdx.x;
    const int tx    = tid & 15;
    const int ty    = tid >> 4;
    const int m0    = ty * 8;
    const int mtile = blockIdx.y * 128;
    const int ntile = blockIdx.x * 128;
    const int kq    = tid & 7;
    const int mrow  = tid >> 3;

    float4 ar[4], br[4];
#pragma unroll
    for (int it = 0; it < 4; it++) {
        const int m = mrow + 32 * it;
        ar[it] = *(const float4*)(A + (size_t)(mtile + m) * 1024 + 4 * kq);
        const int n = ntile + m;
        br[it] = (n < N) ? *(const float4*)(B + (size_t)n * 1024 + 4 * kq)
                         : make_float4(0.f, 0.f, 0.f, 0.f);
    }
#pragma unroll
    for (int it = 0; it < 4; it++) {
        const int m = mrow + 32 * it;
#pragma unroll
        for (int jj = 0; jj < 4; jj++) {
            As[4 * kq + jj][m] = ((const float*)&ar[it])[jj];
            Bs[4 * kq + jj][m] = ((const float*)&br[it])[jj];
        }
    }
    __syncthreads();

    unsigned long long acc[8][4];
#pragma unroll
    for (int i = 0; i < 8; i++)
#pragma unroll
        for (int q = 0; q < 4; q++) acc[i][q] = 0ull;

    for (int kc = 0; kc < 1024; kc += 32) {
        const bool last = (kc + 32 >= 1024);
        if (!last) {
#pragma unroll
            for (int it = 0; it < 4; it++) {
                const int m = mrow + 32 * it;
                ar[it] = *(const float4*)(A + (size_t)(mtile + m) * 1024 + kc + 32 + 4 * kq);
                const int n = ntile + m;
                br[it] = (n < N) ? *(const float4*)(B + (size_t)n * 1024 + kc + 32 + 4 * kq)
                                 : make_float4(0.f, 0.f, 0.f, 0.f);
            }
        }
#pragma unroll
        for (int k = 0; k < 32; k++) {
            float a[8];
            *(float4*)(a)     = *(const float4*)&As[k][m0];
            *(float4*)(a + 4) = *(const float4*)&As[k][m0 + 4];
            unsigned long long bd[4];
#pragma unroll
            for (int q = 0; q < 4; q++)
                bd[q] = *(const unsigned long long*)&Bs[k][2 * tx + 32 * q];
#pragma unroll
            for (int i = 0; i < 8; i++) {
                const unsigned long long ad = dup2(a[i]);
#pragma unroll
                for (int q = 0; q < 4; q++) ffma2(acc[i][q], ad, bd[q]);
            }
        }
        __syncthreads();
        if (!last) {
#pragma unroll
            for (int it = 0; it < 4; it++) {
                const int m = mrow + 32 * it;
#pragma unroll
                for (int jj = 0; jj < 4; jj++) {
                    As[4 * kq + jj][m] = ((const float*)&ar[it])[jj];
                    Bs[4 * kq + jj][m] = ((const float*)&br[it])[jj];
                }
            }
            __syncthreads();
        }
    }

#pragma unroll
    for (int i = 0; i < 8; i++) {
        float* cr = C + (size_t)(mtile + m0 + i) * N;
#pragma unroll
        for (int q = 0; q < 4; q++) {
            const int n = ntile + 2 * tx + 32 * q;
            float lo, hi; unpack2(acc[i][q], lo, hi);
            if (n < N)     cr[n]     = lo + bias[n];
            if (n + 1 < N) cr[n + 1] = hi + bias[n + 1];
        }
    }
}

// state = stack([h1_last, h2_last]) -> out tail (2*B*H elements)
__global__ void copy_state(float* __restrict__ out)
{
    const int i = blockIdx.x * 256 + threadIdx.x;            // 0..131071
    const int base = (SEQ - 1) * BATCH * HID;
    out[i] = (i < BATCH * HID) ? g_y1[base + i] : g_y2[base + i - BATCH * HID];
}

extern "C" void kernel_launch(void* const* d_in, const int* in_sizes, int n_in,
                              void* d_out, int out_size)
{
    const int*   x     = (const int*)  d_in[0];
    const float* W_ih1 = (const float*)d_in[1];
    const float* W_hh1 = (const float*)d_in[2];
    const float* b_ih1 = (const float*)d_in[3];
    const float* b_hh1 = (const float*)d_in[4];
    const float* W_ih2 = (const float*)d_in[5];
    const float* W_hh2 = (const float*)d_in[6];
    const float* b_ih2 = (const float*)d_in[7];
    const float* b_hh2 = (const float*)d_in[8];
    const float* W_fc  = (const float*)d_in[9];
    const float* b_fc  = (const float*)d_in[10];
    float*       out   = (float*)d_out;

    void *py1 = nullptr, *py2 = nullptr, *pxp2 = nullptr;
    cudaGetSymbolAddress(&py1,  g_y1);
    cudaGetSymbolAddress(&py2,  g_y2);
    cudaGetSymbolAddress(&pxp2, g_xp2);

    const int dyn_smem = (8192 + 256 * 33) * 4;   // W slice + reduction = 66560 B
    cudaFuncSetAttribute(rnn_persist<1>, cudaFuncAttributeMaxDynamicSharedMemorySize, dyn_smem);
    cudaFuncSetAttribute(rnn_persist<2>, cudaFuncAttributeMaxDynamicSharedMemorySize, dyn_smem);

    // layer 1 (persistent over all 128 timesteps)
    rnn_persist<1><<<NCTA, 512, dyn_smem>>>(x, W_hh1, b_hh1, W_ih1, b_ih1);

    // xp2 = y1 @ W_ih2^T + b_ih2
    gemm_nt_bias<<<dim3(8, 64), 256>>>((const float*)py1, W_ih2, b_ih2, (float*)pxp2, HID);

    // layer 2 (persistent)
    rnn_persist<2><<<NCTA, 512, dyn_smem>>>(x, W_hh2, b_hh2, W_ih1, b_ih1);

    // logits = y2 @ W_fc^T + b_fc
    gemm_nt_bias<<<dim3(40, 64), 256>>>((const float*)py2, W_fc, b_fc, out, VOCABN);

    copy_state<<<512, 256>>>(out + (size_t)SEQ * BATCH * VOCABN);
}